// round 14
// baseline (speedup 1.0000x reference)
#include <cuda_runtime.h>
#include <cuda_fp16.h>
#include <cstdint>

#define TD 768
#define TO 768
#define TE 8
#define TH 7680
#define TN 4096

#define BM 128
#define BN 128
#define BK 32
#define NTHREADS 256
#define SLD 40                      // smem row stride in fp16 (80 B, 16B-aligned)
#define PLANE_B (128 * SLD * 2)     // 10240
#define STAGE2_B (2 * PLANE_B)      // 20480 (A, Bhi)

// SMEM layout (bytes)
#define SM_BIAS   0
#define SM_PROB   512
#define SM_TILES  1024
#define SM_STAGE  1024                    // epilogue staging reuses tile space
#define SM_T1     (1024 + 32768)          // 33792 (gemm1: tiles 20480 / h-stage 32768)
#define SM_TOTAL2 (1024 + 65536)          // 66560 (gemm2: 2x20480 tiles / fp32 stage 65536)

// ---- scratch ----
__device__ int   g_counts[TE];
__device__ int   g_offsets[TE];
__device__ int   g_rank[TN];
__device__ int   g_eidx[TN];
__device__ float g_prob[TN];
__device__ int   g_perm[TN];
__device__ __half g_h[(size_t)TN * TH];                  // fp16 hidden
__device__ __half g_w2t[(size_t)TE * TO * TH];           // [e][n][k] fp16

// ================= helpers =================
__device__ __forceinline__ uint32_t smem_to_u32(const void* p) {
    uint32_t a;
    asm("{ .reg .u64 t; cvta.to.shared.u64 t, %1; cvt.u32.u64 %0, t; }" : "=r"(a) : "l"(p));
    return a;
}
__device__ __forceinline__ void ldsm4(uint32_t* r, uint32_t addr) {
    asm volatile("ldmatrix.sync.aligned.m8n8.x4.shared.b16 {%0,%1,%2,%3}, [%4];"
                 : "=r"(r[0]), "=r"(r[1]), "=r"(r[2]), "=r"(r[3]) : "r"(addr));
}
__device__ __forceinline__ void mma16816(float* c, const uint32_t* a, const uint32_t* b) {
    asm volatile("mma.sync.aligned.m16n8k16.row.col.f32.f16.f16.f32 "
                 "{%0,%1,%2,%3}, {%4,%5,%6,%7}, {%8,%9}, {%0,%1,%2,%3};"
                 : "+f"(c[0]), "+f"(c[1]), "+f"(c[2]), "+f"(c[3])
                 : "r"(a[0]), "r"(a[1]), "r"(a[2]), "r"(a[3]), "r"(b[0]), "r"(b[1]));
}
__device__ __forceinline__ uint32_t packh2(float a, float b) {
    __half2 h = __floats2half2_rn(a, b);
    return *(uint32_t*)&h;
}

#define CPA16(d, s)  asm volatile("cp.async.ca.shared.global [%0], [%1], 16;" :: "r"(d), "l"(s))
#define CP_COMMIT()  asm volatile("cp.async.commit_group;" ::: "memory")
#define CP_WAIT1()   asm volatile("cp.async.wait_group 1;" ::: "memory")
#define CP_WAIT0()   asm volatile("cp.async.wait_group 0;" ::: "memory")

// ================= gating / routing =================
__global__ void k_zero() {
    if (threadIdx.x < TE) g_counts[threadIdx.x] = 0;
}

__global__ void k_gate(const float* __restrict__ x, const float* __restrict__ Wg,
                       const float* __restrict__ bg) {
    int warp = (blockIdx.x * blockDim.x + threadIdx.x) >> 5;
    int lane = threadIdx.x & 31;
    if (warp >= TN) return;
    const float* xr = x + (size_t)warp * TD;
    float acc[TE];
#pragma unroll
    for (int e = 0; e < TE; e++) acc[e] = 0.f;
    for (int d = lane; d < TD; d += 32) {
        float xv = xr[d];
        const float* wr = Wg + (size_t)d * TE;
#pragma unroll
        for (int e = 0; e < TE; e++) acc[e] += xv * wr[e];
    }
#pragma unroll
    for (int e = 0; e < TE; e++) {
        float v = acc[e];
#pragma unroll
        for (int off = 16; off > 0; off >>= 1) v += __shfl_xor_sync(0xffffffffu, v, off);
        acc[e] = v;
    }
    if (lane == 0) {
        float mx = -1e30f; int am = 0;
#pragma unroll
        for (int e = 0; e < TE; e++) {
            float l = acc[e] + bg[e];
            acc[e] = l;
            if (l > mx) { mx = l; am = e; }
        }
        float s = 0.f;
#pragma unroll
        for (int e = 0; e < TE; e++) s += expf(acc[e] - mx);
        g_eidx[warp] = am;
        g_prob[warp] = 1.f / s;
        g_rank[warp] = atomicAdd(&g_counts[am], 1);
    }
}

__global__ void k_scanscatter() {
    if (threadIdx.x == 0) {
        int o = 0;
#pragma unroll
        for (int e = 0; e < TE; e++) { g_offsets[e] = o; o += g_counts[e]; }
    }
    __syncthreads();
    for (int n = threadIdx.x; n < TN; n += blockDim.x)
        g_perm[g_offsets[g_eidx[n]] + g_rank[n]] = n;
}

// ================= W2 pre-convert: [e][k][n] fp32 -> [e][n][k] fp16 =================
__global__ void k_convert_w2(const float* __restrict__ W2) {
    __shared__ uint16_t shh[32][36];
    const int n0 = blockIdx.x * 32, k0 = blockIdx.y * 32, e = blockIdx.z;
    const float* Wp = W2 + (size_t)e * TH * TO;
    const int t = threadIdx.x, tx = t & 31, ty = t >> 5;
#pragma unroll
    for (int q = 0; q < 4; q++) {
        const int k = ty * 4 + q;
        float v = Wp[(size_t)(k0 + k) * TO + n0 + tx];
        __half hb = __float2half_rn(v);
        shh[tx][k] = *(uint16_t*)&hb;
    }
    __syncthreads();
    const int n = t >> 3, c = t & 7;
    const size_t off = (size_t)e * TO * TH + (size_t)(n0 + n) * TH + k0 + c * 4;
    *(uint2*)((uint16_t*)g_w2t + off) = *(uint2*)&shh[n][c * 4];
}

// ================= single-pass fp16 mma core: D += A*B =================
struct Frag { float c[4][4][4]; };

__device__ __forceinline__ void compute1(uint32_t tb, int wm, int wn, int lane, Frag& F) {
    const uint32_t aoff = ((uint32_t)((wm * 64 + (lane & 15)) * SLD + (lane >> 4) * 8)) * 2;
    const uint32_t boff = ((uint32_t)((wn * 32 + ((lane >> 4) & 1) * 8 + (lane & 7)) * SLD
                                      + ((lane >> 3) & 1) * 8)) * 2;
    const uint32_t aP = tb + aoff;
    const uint32_t bP = tb + PLANE_B + boff;
#pragma unroll
    for (int ks = 0; ks < 2; ks++) {
        const uint32_t kso = ks * 32;
        uint32_t ah[4][4], bh[2][4];
#pragma unroll
        for (int mt = 0; mt < 4; mt++) ldsm4(ah[mt], aP + mt * 16 * SLD * 2 + kso);
#pragma unroll
        for (int p = 0; p < 2; p++) ldsm4(bh[p], bP + p * 16 * SLD * 2 + kso);
#pragma unroll
        for (int mt = 0; mt < 4; mt++)
#pragma unroll
            for (int nt = 0; nt < 4; nt++)
                mma16816(F.c[mt][nt], ah[mt], &bh[nt >> 1][(nt & 1) * 2]);
    }
}

// ================= GEMM1: in-kernel convert, single-pass fp16 =================
__global__ void __launch_bounds__(NTHREADS) k_gemm1(const float* __restrict__ x,
                                                    const float* __restrict__ W1,
                                                    const float* __restrict__ b1) {
    extern __shared__ char smem[];
    const int e   = blockIdx.z;
    const int cnt = g_counts[e];
    const int m0  = blockIdx.y * BM;
    if (m0 >= cnt) return;
    const int n0   = blockIdx.x * BN;
    const int base = g_offsets[e];
    const float* W = W1 + (size_t)e * TD * TH;

    const uint32_t sb = smem_to_u32(smem);
    const int tid = threadIdx.x, wid = tid >> 5, lane = tid & 31;
    const int wm = wid & 1, wn = wid >> 1;

    if (tid < 128) *(float*)(smem + SM_BIAS + tid * 4) = b1[(size_t)e * TH + n0 + tid];

    const int arow = tid >> 1;
    const int half = tid & 1;
    const int arowc = (m0 + arow < cnt) ? (m0 + arow) : (cnt - 1);
    const float* aptr = x + (size_t)g_perm[base + arowc] * TD + half * 16;

    Frag F;
#pragma unroll
    for (int mt = 0; mt < 4; mt++)
#pragma unroll
        for (int nt = 0; nt < 4; nt++)
#pragma unroll
            for (int i = 0; i < 4; i++) F.c[mt][nt][i] = 0.f;

    __syncthreads();
    for (int s = 0; s < TD / BK; s++) {
        const int k0 = s * BK;
        // A fill: 16 fp32 -> 8 packed fp16 words
#pragma unroll
        for (int q = 0; q < 4; q++) {
            float4 v = *(const float4*)(aptr + k0 + q * 4);
            const uint32_t o = ((uint32_t)(arow * SLD + half * 16 + q * 4)) * 2;
            *(uint32_t*)(smem + SM_TILES + o)     = packh2(v.x, v.y);
            *(uint32_t*)(smem + SM_TILES + o + 4) = packh2(v.z, v.w);
        }
        // B fill: W[k][n] fp32 -> Bs[n][k] fp16
#pragma unroll
        for (int it = 0; it < 2; it++) {
            const int tsk = wid + it * 8;
            const int ng = tsk & 3, kg = tsk >> 2;
            const int n = ng * 32 + lane;
            const float* wp = W + (size_t)(k0 + kg * 8) * TH + n0 + n;
            uint32_t hw[4];
#pragma unroll
            for (int kk = 0; kk < 4; kk++)
                hw[kk] = packh2(wp[(size_t)(2 * kk) * TH], wp[(size_t)(2 * kk + 1) * TH]);
            const uint32_t o = ((uint32_t)(n * SLD + kg * 8)) * 2;
            *(uint4*)(smem + SM_TILES + PLANE_B + o) = *(uint4*)hw;
        }
        __syncthreads();
        compute1(sb + SM_TILES, wm, wn, lane, F);
        __syncthreads();
    }

    // epilogue: relu(+bias) -> fp16 staged -> coalesced g_h stores
#pragma unroll
    for (int mt = 0; mt < 4; mt++) {
        const int r0 = wm * 64 + mt * 16 + (lane >> 2);
        const int r1 = r0 + 8;
#pragma unroll
        for (int nt = 0; nt < 4; nt++) {
            const int cp = wn * 16 + nt * 4 + (lane & 3);
            float b0  = *(float*)(smem + SM_BIAS + (2 * cp) * 4);
            float b1v = *(float*)(smem + SM_BIAS + (2 * cp + 1) * 4);
            *(uint32_t*)(smem + SM_STAGE + (r0 * 64 + cp) * 4) =
                packh2(fmaxf(F.c[mt][nt][0] + b0, 0.f), fmaxf(F.c[mt][nt][1] + b1v, 0.f));
            *(uint32_t*)(smem + SM_STAGE + (r1 * 64 + cp) * 4) =
                packh2(fmaxf(F.c[mt][nt][2] + b0, 0.f), fmaxf(F.c[mt][nt][3] + b1v, 0.f));
        }
    }
    __syncthreads();
    {
        const int rr = tid >> 1, part = tid & 1;
        if (rr < cnt - m0) {
            uint16_t* HP = (uint16_t*)g_h + (size_t)(base + m0 + rr) * TH + n0 + part * 64;
#pragma unroll
            for (int j = 0; j < 8; j++) {
                uint4 q = *(uint4*)(smem + SM_STAGE + (rr * 64 + part * 32 + j * 4) * 4);
                *(uint4*)(HP + j * 8) = q;
            }
        }
    }
}

// ================= GEMM2: copy-only cp.async double-buffered, single-pass fp16 =================
__global__ void __launch_bounds__(NTHREADS) k_gemm2(const float* __restrict__ b2,
                                                    float* __restrict__ out) {
    extern __shared__ char smem[];
    const int e   = blockIdx.z;
    const int cnt = g_counts[e];
    const int m0  = blockIdx.y * BM;
    if (m0 >= cnt) return;
    const int n0   = blockIdx.x * BN;
    const int base = g_offsets[e];

    const uint32_t sb = smem_to_u32(smem);
    const int tid = threadIdx.x, wid = tid >> 5, lane = tid & 31;
    const int wm = wid & 1, wn = wid >> 1;

    if (tid < 128) {
        *(float*)(smem + SM_BIAS + tid * 4) = b2[(size_t)e * TO + n0 + tid];
        const int rc = (m0 + tid < cnt) ? (m0 + tid) : (cnt - 1);
        *(float*)(smem + SM_PROB + tid * 4) = g_prob[g_perm[base + rc]];
    }

    const int r = tid >> 1, h = tid & 1;
    const int rowc = (m0 + r < cnt) ? (m0 + r) : (cnt - 1);
    const char* aP = (const char*)(g_h + (size_t)(base + rowc) * TH) + h * 32;
    const char* bP = (const char*)(g_w2t + (size_t)e * TO * TH + (size_t)(n0 + r) * TH) + h * 32;
    const uint32_t dst = sb + SM_TILES + (uint32_t)(r * 80 + h * 32);

    Frag F;
#pragma unroll
    for (int mt = 0; mt < 4; mt++)
#pragma unroll
        for (int nt = 0; nt < 4; nt++)
#pragma unroll
            for (int i = 0; i < 4; i++) F.c[mt][nt][i] = 0.f;

    const int NS = TH / BK;  // 240
    {
        CPA16(dst, aP);                CPA16(dst + 16, aP + 16);
        CPA16(dst + PLANE_B, bP);      CPA16(dst + PLANE_B + 16, bP + 16);
        CP_COMMIT();
    }
    for (int s = 0; s < NS; s++) {
        if (s + 1 < NS) {
            const uint32_t d  = dst + (uint32_t)((s + 1) & 1) * STAGE2_B;
            const uint32_t ko = (uint32_t)(s + 1) * 64;
            CPA16(d, aP + ko);             CPA16(d + 16, aP + ko + 16);
            CPA16(d + PLANE_B, bP + ko);   CPA16(d + PLANE_B + 16, bP + ko + 16);
            CP_COMMIT();
            CP_WAIT1();
        } else {
            CP_WAIT0();
        }
        __syncthreads();
        compute1(sb + SM_TILES + (uint32_t)(s & 1) * STAGE2_B, wm, wn, lane, F);
        __syncthreads();
    }

    // epilogue: (c + bias) * prob -> fp32 stage -> scattered coalesced stores
#pragma unroll
    for (int mt = 0; mt < 4; mt++) {
        const int r0 = wm * 64 + mt * 16 + (lane >> 2);
        const int r1 = r0 + 8;
        const float p0 = *(float*)(smem + SM_PROB + r0 * 4);
        const float p1 = *(float*)(smem + SM_PROB + r1 * 4);
#pragma unroll
        for (int nt = 0; nt < 4; nt++) {
            const int col = wn * 32 + nt * 8 + (lane & 3) * 2;
            float b0  = *(float*)(smem + SM_BIAS + col * 4);
            float b1v = *(float*)(smem + SM_BIAS + (col + 1) * 4);
            *(float*)(smem + SM_STAGE + (r0 * 128 + col) * 4)     = p0 * (F.c[mt][nt][0] + b0);
            *(float*)(smem + SM_STAGE + (r0 * 128 + col + 1) * 4) = p0 * (F.c[mt][nt][1] + b1v);
            *(float*)(smem + SM_STAGE + (r1 * 128 + col) * 4)     = p1 * (F.c[mt][nt][2] + b0);
            *(float*)(smem + SM_STAGE + (r1 * 128 + col + 1) * 4) = p1 * (F.c[mt][nt][3] + b1v);
        }
    }
    __syncthreads();
    {
        const int rr = tid >> 1, part = tid & 1;
        if (rr < cnt - m0) {
            const int token = g_perm[base + m0 + rr];
            float* op = out + (size_t)token * TO + n0 + part * 64;
#pragma unroll
            for (int j = 0; j < 16; j++) {
                float4 q = *(float4*)(smem + SM_STAGE + (rr * 128 + part * 64 + j * 4) * 4);
                *(float4*)(op + j * 4) = q;
            }
        }
    }
}

// ---------------------------------------------------------------
extern "C" void kernel_launch(void* const* d_in, const int* in_sizes, int n_in,
                              void* d_out, int out_size) {
    (void)in_sizes; (void)n_in; (void)out_size;
    const float* x  = (const float*)d_in[0];
    const float* Wg = (const float*)d_in[1];
    const float* bg = (const float*)d_in[2];
    const float* W1 = (const float*)d_in[3];
    const float* b1 = (const float*)d_in[4];
    const float* W2 = (const float*)d_in[5];
    const float* b2 = (const float*)d_in[6];
    float* out = (float*)d_out;

    cudaFuncSetAttribute(k_gemm1, cudaFuncAttributeMaxDynamicSharedMemorySize, SM_T1);
    cudaFuncSetAttribute(k_gemm2, cudaFuncAttributeMaxDynamicSharedMemorySize, SM_TOTAL2);

    k_zero<<<1, 32>>>();
    k_gate<<<(TN * 32 + 255) / 256, 256>>>(x, Wg, bg);
    k_scanscatter<<<1, 256>>>();
    k_gemm1<<<dim3(TH / BN, TN / BM, TE), NTHREADS, SM_T1>>>(x, W1, b1);
    k_convert_w2<<<dim3(TO / 32, TH / 32, TE), 256>>>(W2);
    k_gemm2<<<dim3(TO / BN, TN / BM, TE), NTHREADS, SM_TOTAL2>>>(b2, out);
}

// round 16
// speedup vs baseline: 1.1543x; 1.1543x over previous
#include <cuda_runtime.h>
#include <cuda_fp16.h>
#include <cstdint>

#define TD 768
#define TO 768
#define TE 8
#define TH 7680
#define TN 4096

#define BM 128
#define BN 128
#define BK 32
#define NTHREADS 256
#define SLD 40                      // smem row stride in fp16 (80 B, 16B-aligned)
#define PLANE_B (128 * SLD * 2)     // 10240
#define STAGE2_B (2 * PLANE_B)      // 20480 (A, B)

// SMEM layout (bytes)
#define SM_BIAS   0
#define SM_PROB   512
#define SM_TILES  1024
#define SM_STAGE  1024                    // epilogue staging reuses tile space
#define SM_T1     (1024 + 2 * STAGE2_B)   // 41984 (gemm1: 2-stage tiles / 32KB h-stage)
#define SM_TOTAL2 (1024 + 65536)          // 66560 (gemm2: 2-stage tiles / 64KB fp32 stage)

// ---- scratch (~156 MB total; W1t/W2t share one buffer since their lifetimes
// don't overlap: convert(W1)->gemm1->convert(W2)->gemm2) ----
__device__ int   g_counts[TE];
__device__ int   g_offsets[TE];
__device__ int   g_rank[TN];
__device__ int   g_eidx[TN];
__device__ float g_prob[TN];
__device__ int   g_perm[TN];
__device__ __half g_xp[(size_t)TN * TD];                 // permuted fp16 x (6 MB)
__device__ __half g_h[(size_t)TN * TH];                  // fp16 hidden (60 MB)
__device__ __half g_wt[(size_t)TE * TH * TD];            // shared [e][n][k] fp16 (90 MB)

// ================= helpers =================
__device__ __forceinline__ uint32_t smem_to_u32(const void* p) {
    uint32_t a;
    asm("{ .reg .u64 t; cvta.to.shared.u64 t, %1; cvt.u32.u64 %0, t; }" : "=r"(a) : "l"(p));
    return a;
}
__device__ __forceinline__ void ldsm4(uint32_t* r, uint32_t addr) {
    asm volatile("ldmatrix.sync.aligned.m8n8.x4.shared.b16 {%0,%1,%2,%3}, [%4];"
                 : "=r"(r[0]), "=r"(r[1]), "=r"(r[2]), "=r"(r[3]) : "r"(addr));
}
__device__ __forceinline__ void mma16816(float* c, const uint32_t* a, const uint32_t* b) {
    asm volatile("mma.sync.aligned.m16n8k16.row.col.f32.f16.f16.f32 "
                 "{%0,%1,%2,%3}, {%4,%5,%6,%7}, {%8,%9}, {%0,%1,%2,%3};"
                 : "+f"(c[0]), "+f"(c[1]), "+f"(c[2]), "+f"(c[3])
                 : "r"(a[0]), "r"(a[1]), "r"(a[2]), "r"(a[3]), "r"(b[0]), "r"(b[1]));
}
__device__ __forceinline__ uint32_t packh2(float a, float b) {
    __half2 h = __floats2half2_rn(a, b);
    return *(uint32_t*)&h;
}

#define CPA16(d, s)  asm volatile("cp.async.ca.shared.global [%0], [%1], 16;" :: "r"(d), "l"(s))
#define CP_COMMIT()  asm volatile("cp.async.commit_group;" ::: "memory")
#define CP_WAIT1()   asm volatile("cp.async.wait_group 1;" ::: "memory")
#define CP_WAIT0()   asm volatile("cp.async.wait_group 0;" ::: "memory")

// ================= gating / routing =================
__global__ void k_zero() {
    if (threadIdx.x < TE) g_counts[threadIdx.x] = 0;
}

__global__ void k_gate(const float* __restrict__ x, const float* __restrict__ Wg,
                       const float* __restrict__ bg) {
    int warp = (blockIdx.x * blockDim.x + threadIdx.x) >> 5;
    int lane = threadIdx.x & 31;
    if (warp >= TN) return;
    const float* xr = x + (size_t)warp * TD;
    float acc[TE];
#pragma unroll
    for (int e = 0; e < TE; e++) acc[e] = 0.f;
    for (int d = lane; d < TD; d += 32) {
        float xv = xr[d];
        const float* wr = Wg + (size_t)d * TE;
#pragma unroll
        for (int e = 0; e < TE; e++) acc[e] += xv * wr[e];
    }
#pragma unroll
    for (int e = 0; e < TE; e++) {
        float v = acc[e];
#pragma unroll
        for (int off = 16; off > 0; off >>= 1) v += __shfl_xor_sync(0xffffffffu, v, off);
        acc[e] = v;
    }
    if (lane == 0) {
        float mx = -1e30f; int am = 0;
#pragma unroll
        for (int e = 0; e < TE; e++) {
            float l = acc[e] + bg[e];
            acc[e] = l;
            if (l > mx) { mx = l; am = e; }
        }
        float s = 0.f;
#pragma unroll
        for (int e = 0; e < TE; e++) s += expf(acc[e] - mx);
        g_eidx[warp] = am;
        g_prob[warp] = 1.f / s;
        g_rank[warp] = atomicAdd(&g_counts[am], 1);
    }
}

__global__ void k_scanscatter() {
    if (threadIdx.x == 0) {
        int o = 0;
#pragma unroll
        for (int e = 0; e < TE; e++) { g_offsets[e] = o; o += g_counts[e]; }
    }
    __syncthreads();
    for (int n = threadIdx.x; n < TN; n += blockDim.x)
        g_perm[g_offsets[g_eidx[n]] + g_rank[n]] = n;
}

// ================= pre-converts =================
// x -> permuted fp16. grid = TN, 192 threads.
__global__ void k_convert_x(const float* __restrict__ x) {
    const int pos = blockIdx.x, t = threadIdx.x;
    const int token = g_perm[pos];
    float4 v = *(const float4*)(x + (size_t)token * TD + t * 4);
    uint2 o;
    o.x = packh2(v.x, v.y);
    o.y = packh2(v.z, v.w);
    *(uint2*)((uint16_t*)g_xp + (size_t)pos * TD + t * 4) = o;
}

// W [e][k][n] fp32 -> g_wt [e][n][k] fp16. 32x32 tiles, 256 threads.
__global__ void k_convert_wT(const float* __restrict__ W, int kdim, int ndim) {
    __shared__ uint16_t shh[32][36];
    const int n0 = blockIdx.x * 32, k0 = blockIdx.y * 32, e = blockIdx.z;
    const float* Wp = W + (size_t)e * kdim * ndim;
    const int t = threadIdx.x, tx = t & 31, ty = t >> 5;
#pragma unroll
    for (int q = 0; q < 4; q++) {
        const int k = ty * 4 + q;
        float v = Wp[(size_t)(k0 + k) * ndim + n0 + tx];
        __half hb = __float2half_rn(v);
        shh[tx][k] = *(uint16_t*)&hb;
    }
    __syncthreads();
    const int n = t >> 3, c = t & 7;
    const size_t off = (size_t)e * ndim * kdim + (size_t)(n0 + n) * kdim + k0 + c * 4;
    *(uint2*)((uint16_t*)g_wt + off) = *(uint2*)&shh[n][c * 4];
}

// ================= single-pass fp16 mma core =================
struct Frag { float c[4][4][4]; };

__device__ __forceinline__ void compute1(uint32_t tb, int wm, int wn, int lane, Frag& F) {
    const uint32_t aoff = ((uint32_t)((wm * 64 + (lane & 15)) * SLD + (lane >> 4) * 8)) * 2;
    const uint32_t boff = ((uint32_t)((wn * 32 + ((lane >> 4) & 1) * 8 + (lane & 7)) * SLD
                                      + ((lane >> 3) & 1) * 8)) * 2;
    const uint32_t aP = tb + aoff;
    const uint32_t bP = tb + PLANE_B + boff;
#pragma unroll
    for (int ks = 0; ks < 2; ks++) {
        const uint32_t kso = ks * 32;
        uint32_t ah[4][4], bh[2][4];
#pragma unroll
        for (int mt = 0; mt < 4; mt++) ldsm4(ah[mt], aP + mt * 16 * SLD * 2 + kso);
#pragma unroll
        for (int p = 0; p < 2; p++) ldsm4(bh[p], bP + p * 16 * SLD * 2 + kso);
#pragma unroll
        for (int mt = 0; mt < 4; mt++)
#pragma unroll
            for (int nt = 0; nt < 4; nt++)
                mma16816(F.c[mt][nt], ah[mt], &bh[nt >> 1][(nt & 1) * 2]);
    }
}

// ================= GEMM1: copy-only cp.async double-buffered =================
__global__ void __launch_bounds__(NTHREADS) k_gemm1(const float* __restrict__ b1) {
    extern __shared__ char smem[];
    const int e   = blockIdx.z;
    const int cnt = g_counts[e];
    const int m0  = blockIdx.y * BM;
    if (m0 >= cnt) return;
    const int n0   = blockIdx.x * BN;
    const int base = g_offsets[e];

    const uint32_t sb = smem_to_u32(smem);
    const int tid = threadIdx.x, wid = tid >> 5, lane = tid & 31;
    const int wm = wid & 1, wn = wid >> 1;

    if (tid < 128) *(float*)(smem + SM_BIAS + tid * 4) = b1[(size_t)e * TH + n0 + tid];

    const int r = tid >> 1, h = tid & 1;
    const int rowc = (m0 + r < cnt) ? (m0 + r) : (cnt - 1);
    const char* aP = (const char*)(g_xp + (size_t)(base + rowc) * TD) + h * 32;
    const char* bP = (const char*)(g_wt + (size_t)e * TH * TD + (size_t)(n0 + r) * TD) + h * 32;
    const uint32_t dst = sb + SM_TILES + (uint32_t)(r * 80 + h * 32);

    Frag F;
#pragma unroll
    for (int mt = 0; mt < 4; mt++)
#pragma unroll
        for (int nt = 0; nt < 4; nt++)
#pragma unroll
            for (int i = 0; i < 4; i++) F.c[mt][nt][i] = 0.f;

    const int NS = TD / BK;  // 24
    {
        CPA16(dst, aP);                CPA16(dst + 16, aP + 16);
        CPA16(dst + PLANE_B, bP);      CPA16(dst + PLANE_B + 16, bP + 16);
        CP_COMMIT();
    }
    for (int s = 0; s < NS; s++) {
        if (s + 1 < NS) {
            const uint32_t d  = dst + (uint32_t)((s + 1) & 1) * STAGE2_B;
            const uint32_t ko = (uint32_t)(s + 1) * 64;
            CPA16(d, aP + ko);             CPA16(d + 16, aP + ko + 16);
            CPA16(d + PLANE_B, bP + ko);   CPA16(d + PLANE_B + 16, bP + ko + 16);
            CP_COMMIT();
            CP_WAIT1();
        } else {
            CP_WAIT0();
        }
        __syncthreads();
        compute1(sb + SM_TILES + (uint32_t)(s & 1) * STAGE2_B, wm, wn, lane, F);
        __syncthreads();
    }

    // epilogue: relu(+bias) -> fp16 staged -> coalesced g_h stores
#pragma unroll
    for (int mt = 0; mt < 4; mt++) {
        const int r0 = wm * 64 + mt * 16 + (lane >> 2);
        const int r1 = r0 + 8;
#pragma unroll
        for (int nt = 0; nt < 4; nt++) {
            const int cp = wn * 16 + nt * 4 + (lane & 3);
            float b0  = *(float*)(smem + SM_BIAS + (2 * cp) * 4);
            float b1v = *(float*)(smem + SM_BIAS + (2 * cp + 1) * 4);
            *(uint32_t*)(smem + SM_STAGE + (r0 * 64 + cp) * 4) =
                packh2(fmaxf(F.c[mt][nt][0] + b0, 0.f), fmaxf(F.c[mt][nt][1] + b1v, 0.f));
            *(uint32_t*)(smem + SM_STAGE + (r1 * 64 + cp) * 4) =
                packh2(fmaxf(F.c[mt][nt][2] + b0, 0.f), fmaxf(F.c[mt][nt][3] + b1v, 0.f));
        }
    }
    __syncthreads();
    {
        const int rr = tid >> 1, part = tid & 1;
        if (rr < cnt - m0) {
            uint16_t* HP = (uint16_t*)g_h + (size_t)(base + m0 + rr) * TH + n0 + part * 64;
#pragma unroll
            for (int j = 0; j < 8; j++) {
                uint4 q = *(uint4*)(smem + SM_STAGE + (rr * 64 + part * 32 + j * 4) * 4);
                *(uint4*)(HP + j * 8) = q;
            }
        }
    }
}

// ================= GEMM2: copy-only cp.async double-buffered =================
__global__ void __launch_bounds__(NTHREADS) k_gemm2(const float* __restrict__ b2,
                                                    float* __restrict__ out) {
    extern __shared__ char smem[];
    const int e   = blockIdx.z;
    const int cnt = g_counts[e];
    const int m0  = blockIdx.y * BM;
    if (m0 >= cnt) return;
    const int n0   = blockIdx.x * BN;
    const int base = g_offsets[e];

    const uint32_t sb = smem_to_u32(smem);
    const int tid = threadIdx.x, wid = tid >> 5, lane = tid & 31;
    const int wm = wid & 1, wn = wid >> 1;

    if (tid < 128) {
        *(float*)(smem + SM_BIAS + tid * 4) = b2[(size_t)e * TO + n0 + tid];
        const int rc = (m0 + tid < cnt) ? (m0 + tid) : (cnt - 1);
        *(float*)(smem + SM_PROB + tid * 4) = g_prob[g_perm[base + rc]];
    }

    const int r = tid >> 1, h = tid & 1;
    const int rowc = (m0 + r < cnt) ? (m0 + r) : (cnt - 1);
    const char* aP = (const char*)(g_h + (size_t)(base + rowc) * TH) + h * 32;
    const char* bP = (const char*)(g_wt + (size_t)e * TO * TH + (size_t)(n0 + r) * TH) + h * 32;
    const uint32_t dst = sb + SM_TILES + (uint32_t)(r * 80 + h * 32);

    Frag F;
#pragma unroll
    for (int mt = 0; mt < 4; mt++)
#pragma unroll
        for (int nt = 0; nt < 4; nt++)
#pragma unroll
            for (int i = 0; i < 4; i++) F.c[mt][nt][i] = 0.f;

    const int NS = TH / BK;  // 240
    {
        CPA16(dst, aP);                CPA16(dst + 16, aP + 16);
        CPA16(dst + PLANE_B, bP);      CPA16(dst + PLANE_B + 16, bP + 16);
        CP_COMMIT();
    }
    for (int s = 0; s < NS; s++) {
        if (s + 1 < NS) {
            const uint32_t d  = dst + (uint32_t)((s + 1) & 1) * STAGE2_B;
            const uint32_t ko = (uint32_t)(s + 1) * 64;
            CPA16(d, aP + ko);             CPA16(d + 16, aP + ko + 16);
            CPA16(d + PLANE_B, bP + ko);   CPA16(d + PLANE_B + 16, bP + ko + 16);
            CP_COMMIT();
            CP_WAIT1();
        } else {
            CP_WAIT0();
        }
        __syncthreads();
        compute1(sb + SM_TILES + (uint32_t)(s & 1) * STAGE2_B, wm, wn, lane, F);
        __syncthreads();
    }

    // epilogue: (c + bias) * prob -> fp32 stage -> scattered coalesced stores
#pragma unroll
    for (int mt = 0; mt < 4; mt++) {
        const int r0 = wm * 64 + mt * 16 + (lane >> 2);
        const int r1 = r0 + 8;
        const float p0 = *(float*)(smem + SM_PROB + r0 * 4);
        const float p1 = *(float*)(smem + SM_PROB + r1 * 4);
#pragma unroll
        for (int nt = 0; nt < 4; nt++) {
            const int col = wn * 32 + nt * 8 + (lane & 3) * 2;
            float b0  = *(float*)(smem + SM_BIAS + col * 4);
            float b1v = *(float*)(smem + SM_BIAS + (col + 1) * 4);
            *(float*)(smem + SM_STAGE + (r0 * 128 + col) * 4)     = p0 * (F.c[mt][nt][0] + b0);
            *(float*)(smem + SM_STAGE + (r0 * 128 + col + 1) * 4) = p0 * (F.c[mt][nt][1] + b1v);
            *(float*)(smem + SM_STAGE + (r1 * 128 + col) * 4)     = p1 * (F.c[mt][nt][2] + b0);
            *(float*)(smem + SM_STAGE + (r1 * 128 + col + 1) * 4) = p1 * (F.c[mt][nt][3] + b1v);
        }
    }
    __syncthreads();
    {
        const int rr = tid >> 1, part = tid & 1;
        if (rr < cnt - m0) {
            const int token = g_perm[base + m0 + rr];
            float* op = out + (size_t)token * TO + n0 + part * 64;
#pragma unroll
            for (int j = 0; j < 16; j++) {
                float4 q = *(float4*)(smem + SM_STAGE + (rr * 128 + part * 64 + j * 4) * 4);
                *(float4*)(op + j * 4) = q;
            }
        }
    }
}

// ---------------------------------------------------------------
extern "C" void kernel_launch(void* const* d_in, const int* in_sizes, int n_in,
                              void* d_out, int out_size) {
    (void)in_sizes; (void)n_in; (void)out_size;
    const float* x  = (const float*)d_in[0];
    const float* Wg = (const float*)d_in[1];
    const float* bg = (const float*)d_in[2];
    const float* W1 = (const float*)d_in[3];
    const float* b1 = (const float*)d_in[4];
    const float* W2 = (const float*)d_in[5];
    const float* b2 = (const float*)d_in[6];
    float* out = (float*)d_out;

    cudaFuncSetAttribute(k_gemm1, cudaFuncAttributeMaxDynamicSharedMemorySize, SM_T1);
    cudaFuncSetAttribute(k_gemm2, cudaFuncAttributeMaxDynamicSharedMemorySize, SM_TOTAL2);

    k_zero<<<1, 32>>>();
    k_gate<<<(TN * 32 + 255) / 256, 256>>>(x, Wg, bg);
    k_scanscatter<<<1, 256>>>();
    k_convert_x<<<TN, 192>>>(x);
    k_convert_wT<<<dim3(TH / 32, TD / 32, TE), 256>>>(W1, TD, TH);   // W1 -> g_wt
    k_gemm1<<<dim3(TH / BN, TN / BM, TE), NTHREADS, SM_T1>>>(b1);
    k_convert_wT<<<dim3(TO / 32, TH / 32, TE), 256>>>(W2, TH, TO);   // W2 -> g_wt (reuse)
    k_gemm2<<<dim3(TO / BN, TN / BM, TE), NTHREADS, SM_TOTAL2>>>(b2, out);
}

// round 17
// speedup vs baseline: 1.1687x; 1.0125x over previous
#include <cuda_runtime.h>
#include <cuda_fp16.h>
#include <cstdint>

#define TD 768
#define TO 768
#define TE 8
#define TH 7680
#define TN 4096

#define BM 128
#define BN 128
#define BK 64
#define NTHREADS 256
#define SLD 72                      // smem row stride in fp16 (144 B; conflict-free, 16B-aligned)
#define PLANE_B (128 * SLD * 2)     // 18432
#define STAGE2_B (2 * PLANE_B)      // 36864 (A, B)

// SMEM layout (bytes)
#define SM_BIAS   0
#define SM_PROB   512
#define SM_TILES  1024
#define SM_STAGE  1024                    // epilogue staging reuses tile space
#define SM_TOTAL  (1024 + 2 * STAGE2_B)   // 74752 (both gemms; stage area 73728 >= 64KB)

// ---- scratch (~156 MB; W1t/W2t share one buffer: convert(W1)->gemm1->convert(W2)->gemm2) ----
__device__ int   g_counts[TE];
__device__ int   g_offsets[TE];
__device__ int   g_rank[TN];
__device__ int   g_eidx[TN];
__device__ float g_prob[TN];
__device__ int   g_perm[TN];
__device__ __half g_x16[(size_t)TN * TD];                // fp16 x, token order (6 MB)
__device__ __half g_h[(size_t)TN * TH];                  // fp16 hidden (60 MB)
__device__ __half g_wt[(size_t)TE * TH * TD];            // shared [e][n][k] fp16 (90 MB)

// ================= helpers =================
__device__ __forceinline__ uint32_t smem_to_u32(const void* p) {
    uint32_t a;
    asm("{ .reg .u64 t; cvta.to.shared.u64 t, %1; cvt.u32.u64 %0, t; }" : "=r"(a) : "l"(p));
    return a;
}
__device__ __forceinline__ void ldsm4(uint32_t* r, uint32_t addr) {
    asm volatile("ldmatrix.sync.aligned.m8n8.x4.shared.b16 {%0,%1,%2,%3}, [%4];"
                 : "=r"(r[0]), "=r"(r[1]), "=r"(r[2]), "=r"(r[3]) : "r"(addr));
}
__device__ __forceinline__ void mma16816(float* c, const uint32_t* a, const uint32_t* b) {
    asm volatile("mma.sync.aligned.m16n8k16.row.col.f32.f16.f16.f32 "
                 "{%0,%1,%2,%3}, {%4,%5,%6,%7}, {%8,%9}, {%0,%1,%2,%3};"
                 : "+f"(c[0]), "+f"(c[1]), "+f"(c[2]), "+f"(c[3])
                 : "r"(a[0]), "r"(a[1]), "r"(a[2]), "r"(a[3]), "r"(b[0]), "r"(b[1]));
}
__device__ __forceinline__ uint32_t packh2(float a, float b) {
    __half2 h = __floats2half2_rn(a, b);
    return *(uint32_t*)&h;
}

#define CPA16(d, s)  asm volatile("cp.async.ca.shared.global [%0], [%1], 16;" :: "r"(d), "l"(s))
#define CP_COMMIT()  asm volatile("cp.async.commit_group;" ::: "memory")
#define CP_WAIT1()   asm volatile("cp.async.wait_group 1;" ::: "memory")
#define CP_WAIT0()   asm volatile("cp.async.wait_group 0;" ::: "memory")

// ================= gating / routing (also emits fp16 x) =================
__global__ void k_zero() {
    if (threadIdx.x < TE) g_counts[threadIdx.x] = 0;
}

__global__ void k_gate(const float* __restrict__ x, const float* __restrict__ Wg,
                       const float* __restrict__ bg) {
    int warp = (blockIdx.x * blockDim.x + threadIdx.x) >> 5;
    int lane = threadIdx.x & 31;
    if (warp >= TN) return;
    const float* xr = x + (size_t)warp * TD;
    uint16_t* xo = (uint16_t*)g_x16 + (size_t)warp * TD;
    float acc[TE];
#pragma unroll
    for (int e = 0; e < TE; e++) acc[e] = 0.f;
    for (int d = lane; d < TD; d += 32) {
        float xv = xr[d];
        __half hv = __float2half_rn(xv);
        xo[d] = *(uint16_t*)&hv;
        const float* wr = Wg + (size_t)d * TE;
#pragma unroll
        for (int e = 0; e < TE; e++) acc[e] += xv * wr[e];
    }
#pragma unroll
    for (int e = 0; e < TE; e++) {
        float v = acc[e];
#pragma unroll
        for (int off = 16; off > 0; off >>= 1) v += __shfl_xor_sync(0xffffffffu, v, off);
        acc[e] = v;
    }
    if (lane == 0) {
        float mx = -1e30f; int am = 0;
#pragma unroll
        for (int e = 0; e < TE; e++) {
            float l = acc[e] + bg[e];
            acc[e] = l;
            if (l > mx) { mx = l; am = e; }
        }
        float s = 0.f;
#pragma unroll
        for (int e = 0; e < TE; e++) s += expf(acc[e] - mx);
        g_eidx[warp] = am;
        g_prob[warp] = 1.f / s;
        g_rank[warp] = atomicAdd(&g_counts[am], 1);
    }
}

__global__ void k_scanscatter() {
    if (threadIdx.x == 0) {
        int o = 0;
#pragma unroll
        for (int e = 0; e < TE; e++) { g_offsets[e] = o; o += g_counts[e]; }
    }
    __syncthreads();
    for (int n = threadIdx.x; n < TN; n += blockDim.x)
        g_perm[g_offsets[g_eidx[n]] + g_rank[n]] = n;
}

// W [e][k][n] fp32 -> g_wt [e][n][k] fp16. 32x32 tiles, 256 threads.
__global__ void k_convert_wT(const float* __restrict__ W, int kdim, int ndim) {
    __shared__ uint16_t shh[32][36];
    const int n0 = blockIdx.x * 32, k0 = blockIdx.y * 32, e = blockIdx.z;
    const float* Wp = W + (size_t)e * kdim * ndim;
    const int t = threadIdx.x, tx = t & 31, ty = t >> 5;
#pragma unroll
    for (int q = 0; q < 4; q++) {
        const int k = ty * 4 + q;
        float v = Wp[(size_t)(k0 + k) * ndim + n0 + tx];
        __half hb = __float2half_rn(v);
        shh[tx][k] = *(uint16_t*)&hb;
    }
    __syncthreads();
    const int n = t >> 3, c = t & 7;
    const size_t off = (size_t)e * ndim * kdim + (size_t)(n0 + n) * kdim + k0 + c * 4;
    *(uint2*)((uint16_t*)g_wt + off) = *(uint2*)&shh[n][c * 4];
}

// ================= single-pass fp16 mma core over BK=64 =================
struct Frag { float c[4][4][4]; };

__device__ __forceinline__ void compute1(uint32_t tb, int wm, int wn, int lane, Frag& F) {
    const uint32_t aoff = ((uint32_t)((wm * 64 + (lane & 15)) * SLD + (lane >> 4) * 8)) * 2;
    const uint32_t boff = ((uint32_t)((wn * 32 + ((lane >> 4) & 1) * 8 + (lane & 7)) * SLD
                                      + ((lane >> 3) & 1) * 8)) * 2;
    const uint32_t aP = tb + aoff;
    const uint32_t bP = tb + PLANE_B + boff;
#pragma unroll
    for (int ks = 0; ks < 4; ks++) {
        const uint32_t kso = ks * 32;   // 16 fp16 per chunk
        uint32_t ah[4][4], bh[2][4];
#pragma unroll
        for (int mt = 0; mt < 4; mt++) ldsm4(ah[mt], aP + mt * 16 * SLD * 2 + kso);
#pragma unroll
        for (int p = 0; p < 2; p++) ldsm4(bh[p], bP + p * 16 * SLD * 2 + kso);
#pragma unroll
        for (int mt = 0; mt < 4; mt++)
#pragma unroll
            for (int nt = 0; nt < 4; nt++)
                mma16816(F.c[mt][nt], ah[mt], &bh[nt >> 1][(nt & 1) * 2]);
    }
}

// per-thread fill: 64B of A-row + 64B of B-row (4+4 cp.async)
__device__ __forceinline__ void fill64(uint32_t d, const char* aP, const char* bP,
                                       uint32_t ko) {
    CPA16(d,      aP + ko);      CPA16(d + 16, aP + ko + 16);
    CPA16(d + 32, aP + ko + 32); CPA16(d + 48, aP + ko + 48);
    const uint32_t db = d + PLANE_B;
    CPA16(db,      bP + ko);      CPA16(db + 16, bP + ko + 16);
    CPA16(db + 32, bP + ko + 32); CPA16(db + 48, bP + ko + 48);
}

// ================= GEMM1: copy-only cp.async double-buffered =================
__global__ void __launch_bounds__(NTHREADS) k_gemm1(const float* __restrict__ b1) {
    extern __shared__ char smem[];
    const int e   = blockIdx.z;
    const int cnt = g_counts[e];
    const int m0  = blockIdx.y * BM;
    if (m0 >= cnt) return;
    const int n0   = blockIdx.x * BN;
    const int base = g_offsets[e];

    const uint32_t sb = smem_to_u32(smem);
    const int tid = threadIdx.x, wid = tid >> 5, lane = tid & 31;
    const int wm = wid & 1, wn = wid >> 1;

    if (tid < 128) *(float*)(smem + SM_BIAS + tid * 4) = b1[(size_t)e * TH + n0 + tid];

    const int r = tid >> 1, h = tid & 1;
    const int rowc = (m0 + r < cnt) ? (m0 + r) : (cnt - 1);
    const int token = g_perm[base + rowc];
    const char* aP = (const char*)(g_x16 + (size_t)token * TD) + h * 64;
    const char* bP = (const char*)(g_wt + (size_t)e * TH * TD + (size_t)(n0 + r) * TD) + h * 64;
    const uint32_t dst = sb + SM_TILES + (uint32_t)(r * 144 + h * 64);

    Frag F;
#pragma unroll
    for (int mt = 0; mt < 4; mt++)
#pragma unroll
        for (int nt = 0; nt < 4; nt++)
#pragma unroll
            for (int i = 0; i < 4; i++) F.c[mt][nt][i] = 0.f;

    const int NS = TD / BK;  // 12
    fill64(dst, aP, bP, 0);
    CP_COMMIT();
    for (int s = 0; s < NS; s++) {
        if (s + 1 < NS) {
            fill64(dst + (uint32_t)((s + 1) & 1) * STAGE2_B, aP, bP, (uint32_t)(s + 1) * 128);
            CP_COMMIT();
            CP_WAIT1();
        } else {
            CP_WAIT0();
        }
        __syncthreads();
        compute1(sb + SM_TILES + (uint32_t)(s & 1) * STAGE2_B, wm, wn, lane, F);
        __syncthreads();
    }

    // epilogue: relu(+bias) -> fp16 staged -> coalesced g_h stores
#pragma unroll
    for (int mt = 0; mt < 4; mt++) {
        const int r0 = wm * 64 + mt * 16 + (lane >> 2);
        const int r1 = r0 + 8;
#pragma unroll
        for (int nt = 0; nt < 4; nt++) {
            const int cp = wn * 16 + nt * 4 + (lane & 3);
            float b0  = *(float*)(smem + SM_BIAS + (2 * cp) * 4);
            float b1v = *(float*)(smem + SM_BIAS + (2 * cp + 1) * 4);
            *(uint32_t*)(smem + SM_STAGE + (r0 * 64 + cp) * 4) =
                packh2(fmaxf(F.c[mt][nt][0] + b0, 0.f), fmaxf(F.c[mt][nt][1] + b1v, 0.f));
            *(uint32_t*)(smem + SM_STAGE + (r1 * 64 + cp) * 4) =
                packh2(fmaxf(F.c[mt][nt][2] + b0, 0.f), fmaxf(F.c[mt][nt][3] + b1v, 0.f));
        }
    }
    __syncthreads();
    {
        const int rr = tid >> 1, part = tid & 1;
        if (rr < cnt - m0) {
            uint16_t* HP = (uint16_t*)g_h + (size_t)(base + m0 + rr) * TH + n0 + part * 64;
#pragma unroll
            for (int j = 0; j < 8; j++) {
                uint4 q = *(uint4*)(smem + SM_STAGE + (rr * 64 + part * 32 + j * 4) * 4);
                *(uint4*)(HP + j * 8) = q;
            }
        }
    }
}

// ================= GEMM2: copy-only cp.async double-buffered =================
__global__ void __launch_bounds__(NTHREADS) k_gemm2(const float* __restrict__ b2,
                                                    float* __restrict__ out) {
    extern __shared__ char smem[];
    const int e   = blockIdx.z;
    const int cnt = g_counts[e];
    const int m0  = blockIdx.y * BM;
    if (m0 >= cnt) return;
    const int n0   = blockIdx.x * BN;
    const int base = g_offsets[e];

    const uint32_t sb = smem_to_u32(smem);
    const int tid = threadIdx.x, wid = tid >> 5, lane = tid & 31;
    const int wm = wid & 1, wn = wid >> 1;

    if (tid < 128) {
        *(float*)(smem + SM_BIAS + tid * 4) = b2[(size_t)e * TO + n0 + tid];
        const int rc = (m0 + tid < cnt) ? (m0 + tid) : (cnt - 1);
        *(float*)(smem + SM_PROB + tid * 4) = g_prob[g_perm[base + rc]];
    }

    const int r = tid >> 1, h = tid & 1;
    const int rowc = (m0 + r < cnt) ? (m0 + r) : (cnt - 1);
    const char* aP = (const char*)(g_h + (size_t)(base + rowc) * TH) + h * 64;
    const char* bP = (const char*)(g_wt + (size_t)e * TO * TH + (size_t)(n0 + r) * TH) + h * 64;
    const uint32_t dst = sb + SM_TILES + (uint32_t)(r * 144 + h * 64);

    Frag F;
#pragma unroll
    for (int mt = 0; mt < 4; mt++)
#pragma unroll
        for (int nt = 0; nt < 4; nt++)
#pragma unroll
            for (int i = 0; i < 4; i++) F.c[mt][nt][i] = 0.f;

    const int NS = TH / BK;  // 120
    fill64(dst, aP, bP, 0);
    CP_COMMIT();
    for (int s = 0; s < NS; s++) {
        if (s + 1 < NS) {
            fill64(dst + (uint32_t)((s + 1) & 1) * STAGE2_B, aP, bP, (uint32_t)(s + 1) * 128);
            CP_COMMIT();
            CP_WAIT1();
        } else {
            CP_WAIT0();
        }
        __syncthreads();
        compute1(sb + SM_TILES + (uint32_t)(s & 1) * STAGE2_B, wm, wn, lane, F);
        __syncthreads();
    }

    // epilogue: (c + bias) * prob -> fp32 stage -> scattered coalesced stores
#pragma unroll
    for (int mt = 0; mt < 4; mt++) {
        const int r0 = wm * 64 + mt * 16 + (lane >> 2);
        const int r1 = r0 + 8;
        const float p0 = *(float*)(smem + SM_PROB + r0 * 4);
        const float p1 = *(float*)(smem + SM_PROB + r1 * 4);
#pragma unroll
        for (int nt = 0; nt < 4; nt++) {
            const int col = wn * 32 + nt * 8 + (lane & 3) * 2;
            float b0  = *(float*)(smem + SM_BIAS + col * 4);
            float b1v = *(float*)(smem + SM_BIAS + (col + 1) * 4);
            *(float*)(smem + SM_STAGE + (r0 * 128 + col) * 4)     = p0 * (F.c[mt][nt][0] + b0);
            *(float*)(smem + SM_STAGE + (r0 * 128 + col + 1) * 4) = p0 * (F.c[mt][nt][1] + b1v);
            *(float*)(smem + SM_STAGE + (r1 * 128 + col) * 4)     = p1 * (F.c[mt][nt][2] + b0);
            *(float*)(smem + SM_STAGE + (r1 * 128 + col + 1) * 4) = p1 * (F.c[mt][nt][3] + b1v);
        }
    }
    __syncthreads();
    {
        const int rr = tid >> 1, part = tid & 1;
        if (rr < cnt - m0) {
            const int token = g_perm[base + m0 + rr];
            float* op = out + (size_t)token * TO + n0 + part * 64;
#pragma unroll
            for (int j = 0; j < 16; j++) {
                float4 q = *(float4*)(smem + SM_STAGE + (rr * 128 + part * 64 + j * 4) * 4);
                *(float4*)(op + j * 4) = q;
            }
        }
    }
}

// ---------------------------------------------------------------
extern "C" void kernel_launch(void* const* d_in, const int* in_sizes, int n_in,
                              void* d_out, int out_size) {
    (void)in_sizes; (void)n_in; (void)out_size;
    const float* x  = (const float*)d_in[0];
    const float* Wg = (const float*)d_in[1];
    const float* bg = (const float*)d_in[2];
    const float* W1 = (const float*)d_in[3];
    const float* b1 = (const float*)d_in[4];
    const float* W2 = (const float*)d_in[5];
    const float* b2 = (const float*)d_in[6];
    float* out = (float*)d_out;

    cudaFuncSetAttribute(k_gemm1, cudaFuncAttributeMaxDynamicSharedMemorySize, SM_TOTAL);
    cudaFuncSetAttribute(k_gemm2, cudaFuncAttributeMaxDynamicSharedMemorySize, SM_TOTAL);

    k_zero<<<1, 32>>>();
    k_gate<<<(TN * 32 + 255) / 256, 256>>>(x, Wg, bg);
    k_scanscatter<<<1, 256>>>();
    k_convert_wT<<<dim3(TH / 32, TD / 32, TE), 256>>>(W1, TD, TH);   // W1 -> g_wt
    k_gemm1<<<dim3(TH / BN, TN / BM, TE), NTHREADS, SM_TOTAL>>>(b1);
    k_convert_wT<<<dim3(TO / 32, TH / 32, TE), 256>>>(W2, TH, TO);   // W2 -> g_wt (reuse)
    k_gemm2<<<dim3(TO / BN, TN / BM, TE), NTHREADS, SM_TOTAL>>>(b2, out);
}